// round 3
// baseline (speedup 1.0000x reference)
#include <cuda_runtime.h>

#define KC 120
#define DC 128
#define NMAX 262144

// ---------------- device scratch (no allocations allowed) ----------------
__device__ float  g_cent[2][KC * DC];
__device__ float  g_csq[2][KC];
__device__ float  g_sums[KC * DC];
__device__ float  g_counts[KC];
__device__ int    g_labels[2][NMAX];
__device__ double g_acc[2];

// ---------------- f32x2 packed helpers (ptxas never emits FFMA2 from C++) ----
__device__ __forceinline__ unsigned long long pack2(float a, float b) {
    unsigned long long r;
    asm("mov.b64 %0, {%1, %2};" : "=l"(r)
        : "r"(__float_as_uint(a)), "r"(__float_as_uint(b)));
    return r;
}
__device__ __forceinline__ void fma2(unsigned long long& d,
                                     unsigned long long a,
                                     unsigned long long b) {
    asm("fma.rn.f32x2 %0, %1, %2, %0;" : "+l"(d) : "l"(a), "l"(b));
}
__device__ __forceinline__ float sum2(unsigned long long a) {
    unsigned int lo, hi;
    asm("mov.b64 {%0, %1}, %2;" : "=r"(lo), "=r"(hi) : "l"(a));
    return __uint_as_float(lo) + __uint_as_float(hi);
}

// ---------------- centroid init / update (+ c_sq, zero scratch) ----------
// mode 0: cent = x[:K] ; mode 1: cent = sums / max(counts,1-if-0)
__global__ void centroid_kernel(const float* __restrict__ x, int set, int mode) {
    int k = blockIdx.x;
    int d = threadIdx.x;
    float c;
    if (mode == 0) {
        c = x[k * DC + d];
    } else {
        float cnt = g_counts[k];
        if (cnt == 0.0f) cnt = 1.0f;
        c = g_sums[k * DC + d] / cnt;
    }
    g_cent[set][k * DC + d] = c;
    g_sums[k * DC + d] = 0.0f;
    if (d == 0) g_counts[k] = 0.0f;

    float v = c * c;
    #pragma unroll
    for (int o = 16; o > 0; o >>= 1) v += __shfl_down_sync(0xffffffffu, v, o);
    __shared__ float r[4];
    if ((d & 31) == 0) r[d >> 5] = v;
    __syncthreads();
    if (d == 0) g_csq[set][k] = r[0] + r[1] + r[2] + r[3];
}

// ---------------- assignment: argmin_k ||x-c_k||^2 -----------------------
__global__ __launch_bounds__(256, 1)
void assign_kernel(const float* __restrict__ x, int set, int N) {
    extern __shared__ float sm[];
    float* sc   = sm;            // KC*DC centroids
    float* scsq = sm + KC * DC;  // KC

    const float* cent = g_cent[set];
    for (int i = threadIdx.x; i < KC * DC; i += 256) sc[i] = cent[i];
    for (int i = threadIdx.x; i < KC; i += 256) scsq[i] = g_csq[set][i];
    __syncthreads();

    int p = blockIdx.x * 256 + threadIdx.x;
    if (p >= N) return;

    unsigned long long xv[DC / 2];
    float xsq = 0.0f;
    const float4* xr = (const float4*)(x + (size_t)p * DC);
    #pragma unroll
    for (int i = 0; i < DC / 4; i++) {
        float4 v = xr[i];
        xsq = fmaf(v.x, v.x, xsq);
        xsq = fmaf(v.y, v.y, xsq);
        xsq = fmaf(v.z, v.z, xsq);
        xsq = fmaf(v.w, v.w, xsq);
        xv[2 * i]     = pack2(v.x, v.y);
        xv[2 * i + 1] = pack2(v.z, v.w);
    }

    float best = 3.4e38f;
    int bi = 0;
    #pragma unroll 2
    for (int k = 0; k < KC; k++) {
        const ulonglong2* cp = (const ulonglong2*)(sc + k * DC);
        unsigned long long a0 = 0ull, a1 = 0ull, a2 = 0ull, a3 = 0ull;
        #pragma unroll
        for (int i = 0; i < DC / 4; i++) {
            ulonglong2 cc = cp[i];
            if (i & 1) { fma2(a2, xv[2 * i], cc.x); fma2(a3, xv[2 * i + 1], cc.y); }
            else       { fma2(a0, xv[2 * i], cc.x); fma2(a1, xv[2 * i + 1], cc.y); }
        }
        float dot = (sum2(a0) + sum2(a1)) + (sum2(a2) + sum2(a3));
        float dist = xsq - 2.0f * dot + scsq[k];
        if (dist < best) { best = dist; bi = k; }  // strict < => first-index ties
    }
    g_labels[set][p] = bi;
}

// ---------------- scatter reduce: sums[k][d] += x, counts[k] += 1 --------
// dim-owner scheme: warp lanes own dims (conflict-free), labels broadcast.
// Two privatized smem copies (warps 0-3 vs 4-7) to double RMW-latency chains.
__global__ __launch_bounds__(256, 1)
void reduce_kernel(const float* __restrict__ x, int set, int N) {
    extern __shared__ float sm[];
    float* sumA = sm;
    float* sumB = sm + KC * DC;
    float* scnt = sm + 2 * KC * DC;

    int tid = threadIdx.x;
    for (int i = tid; i < 2 * KC * DC; i += 256) sm[i] = 0.0f;
    for (int i = tid; i < KC; i += 256) scnt[i] = 0.0f;
    __syncthreads();

    const int* __restrict__ lab = g_labels[set];
    int G = gridDim.x;
    int per = (N + G - 1) / G;
    int p0 = blockIdx.x * per;
    int p1 = min(N, p0 + per);

    int half = tid >> 7;     // 0 or 1 (uniform per warp)
    int d = tid & 127;
    float* mysum = half ? sumB : sumA;
    int pm = p0 + ((p1 - p0) >> 1);
    int qs = half ? pm : p0;
    int qe = half ? p1 : pm;

    int p = qs;
    for (; p + 4 <= qe; p += 4) {
        int l0 = lab[p], l1 = lab[p + 1], l2 = lab[p + 2], l3 = lab[p + 3];
        float v0 = x[(size_t)(p)     * DC + d];
        float v1 = x[(size_t)(p + 1) * DC + d];
        float v2 = x[(size_t)(p + 2) * DC + d];
        float v3 = x[(size_t)(p + 3) * DC + d];
        mysum[l0 * DC + d] += v0;
        mysum[l1 * DC + d] += v1;
        mysum[l2 * DC + d] += v2;
        mysum[l3 * DC + d] += v3;
    }
    for (; p < qe; ++p) {
        mysum[lab[p] * DC + d] += x[(size_t)p * DC + d];
    }

    // counts (spread smem atomics, trivial volume)
    for (int q = p0 + tid; q < p1; q += 256)
        atomicAdd(&scnt[lab[q]], 1.0f);
    __syncthreads();

    for (int i = tid; i < KC * DC; i += 256)
        atomicAdd(&g_sums[i], sumA[i] + sumB[i]);
    for (int i = tid; i < KC; i += 256)
        atomicAdd(&g_counts[i], scnt[i]);
}

// ---------------- cross entropy: CE_i = logsumexp(x_i.C^T/T) - logit[lab] --
__global__ __launch_bounds__(256, 1)
void ce_kernel(const float* __restrict__ x, int cset, int aidx, int N) {
    extern __shared__ float sm[];
    float* sc = sm;
    const float* cent = g_cent[cset];
    for (int i = threadIdx.x; i < KC * DC; i += 256) sc[i] = cent[i];
    __syncthreads();

    int p = blockIdx.x * 256 + threadIdx.x;
    bool valid = p < N;
    int pp = valid ? p : 0;

    unsigned long long xv[DC / 2];
    const float4* xr = (const float4*)(x + (size_t)pp * DC);
    #pragma unroll
    for (int i = 0; i < DC / 4; i++) {
        float4 v = xr[i];
        xv[2 * i]     = pack2(v.x, v.y);
        xv[2 * i + 1] = pack2(v.z, v.w);
    }
    int lab = g_labels[cset][pp];

    float m = -3.0e38f, ssum = 0.0f, lablg = 0.0f;
    #pragma unroll 2
    for (int k = 0; k < KC; k++) {
        const ulonglong2* cp = (const ulonglong2*)(sc + k * DC);
        unsigned long long a0 = 0ull, a1 = 0ull, a2 = 0ull, a3 = 0ull;
        #pragma unroll
        for (int i = 0; i < DC / 4; i++) {
            ulonglong2 cc = cp[i];
            if (i & 1) { fma2(a2, xv[2 * i], cc.x); fma2(a3, xv[2 * i + 1], cc.y); }
            else       { fma2(a0, xv[2 * i], cc.x); fma2(a1, xv[2 * i + 1], cc.y); }
        }
        float dot = (sum2(a0) + sum2(a1)) + (sum2(a2) + sum2(a3));
        float lg = dot * 2.5f;             // / CLD_T (0.4)
        if (k == lab) lablg = lg;
        float nm = fmaxf(m, lg);
        ssum = ssum * __expf(m - nm) + __expf(lg - nm);
        m = nm;
    }
    float ce = valid ? (m + logf(ssum) - lablg) : 0.0f;

    // block reduce -> double atomic
    #pragma unroll
    for (int o = 16; o > 0; o >>= 1) ce += __shfl_down_sync(0xffffffffu, ce, o);
    __shared__ float rr[8];
    if ((threadIdx.x & 31) == 0) rr[threadIdx.x >> 5] = ce;
    __syncthreads();
    if (threadIdx.x == 0) {
        float t = 0.0f;
        #pragma unroll
        for (int i = 0; i < 8; i++) t += rr[i];
        atomicAdd(&g_acc[aidx], (double)t);
    }
}

__global__ void zero_acc_kernel() {
    if (threadIdx.x < 2) g_acc[threadIdx.x] = 0.0;
}

__global__ void finalize_kernel(float* out, int N) {
    out[0] = (float)((g_acc[0] + g_acc[1]) / (2.0 * (double)N));
}

// ---------------- launch ------------------------------------------------
extern "C" void kernel_launch(void* const* d_in, const int* in_sizes, int n_in,
                              void* d_out, int out_size) {
    const float* f1 = (const float*)d_in[0];
    const float* f2 = (const float*)d_in[1];
    int N = in_sizes[0] / DC;

    const int ASSIGN_SMEM = (KC * DC + KC) * (int)sizeof(float);       // 61,920 B
    const int REDUCE_SMEM = (2 * KC * DC + KC) * (int)sizeof(float);   // 123,360 B

    cudaFuncSetAttribute(assign_kernel, cudaFuncAttributeMaxDynamicSharedMemorySize, ASSIGN_SMEM);
    cudaFuncSetAttribute(ce_kernel,     cudaFuncAttributeMaxDynamicSharedMemorySize, ASSIGN_SMEM);
    cudaFuncSetAttribute(reduce_kernel, cudaFuncAttributeMaxDynamicSharedMemorySize, REDUCE_SMEM);

    int agrid = (N + 255) / 256;

    for (int s = 0; s < 2; ++s) {
        const float* x = s ? f2 : f1;
        centroid_kernel<<<KC, DC>>>(x, s, 0);      // init c = x[:K], csq, zero sums
        for (int it = 0; it < 5; ++it) {
            assign_kernel<<<agrid, 256, ASSIGN_SMEM>>>(x, s, N);
            reduce_kernel<<<128, 256, REDUCE_SMEM>>>(x, s, N);
            centroid_kernel<<<KC, DC>>>(nullptr, s, 1);
        }
    }
    zero_acc_kernel<<<1, 32>>>();
    ce_kernel<<<agrid, 256, ASSIGN_SMEM>>>(f1, 1, 0, N);  // f1 vs c2 / cl2
    ce_kernel<<<agrid, 256, ASSIGN_SMEM>>>(f2, 0, 1, N);  // f2 vs c1 / cl1
    finalize_kernel<<<1, 1>>>((float*)d_out, N);
}